// round 16
// baseline (speedup 1.0000x reference)
#include <cuda_runtime.h>
#include <cstdint>

typedef unsigned long long ull;
typedef long long ll;
typedef unsigned int uint;

// Problem dims
#define Nn   64
#define CI   128
#define Hh   56
#define Ww   56
#define CO   256
#define OH   28
#define OW   28
#define M_EL (Nn*OH*OW)
#define NOUT (Nn*CO*OH*OW)

// ---------------- device scratch ----------------
__device__ uint   g_xbits [Nn*4*Hh*Ww];     // [n][cw(4)][h][w]
__device__ uint   g_x2bits[Nn*8*OH*OW];     // [n][cw(8)][oh][ow]
__device__ uint   g_w1bits[3*4*CO*4];       // [kh][cw][co][kw(4, pad=0)]
__device__ uint   g_w2bits[3*8*CO*4];       // [kh][cw][co][kw(4, pad=0)]
__device__ uint   g_wsbits[CO*4];           // [co][cw(4)]
__device__ short  g_S1t[NOUT];              // [n][oh][ow][co]
__device__ short  g_S2[NOUT];               // NCHW
__device__ short  g_Ss[NOUT];               // NCHW
__device__ ull    g_acc1[2*CO];
__device__ ull    g_acc2[5*CO];
__device__ double g_part[3][64];
__device__ float  g_bn1a[CO], g_bn1b[CO];
__device__ float  g_A[CO], g_B[CO], g_T[CO];

// ---------------- fused front: alpha partials + weight pack + x pack ----------------
__global__ void __launch_bounds__(256) k_front(const float* x, const float* w1,
                                               const float* w2, const float* ws) {
    __shared__ double sm[256];
    __shared__ unsigned char sb[CI][Ww];
    const int b = blockIdx.x;

    if (b < 192) {                       // ---- alpha stage 1 ----
        if (b == 0) {
            for (int i = threadIdx.x; i < 2*CO; i += 256) g_acc1[i] = 0ull;
            for (int i = threadIdx.x; i < 5*CO; i += 256) g_acc2[i] = 0ull;
        }
        int g = b >> 6, p = b & 63;
        const float* ptr; int n;
        if (g == 0)      { ptr = w1; n = CO*CI*9; }
        else if (g == 1) { ptr = w2; n = CO*CO*9; }
        else             { ptr = ws; n = CO*CI;   }
        float a0 = 0.f, a1 = 0.f;
        int stride = 64*256*2;
        for (int i = p*512 + threadIdx.x; i < n; i += stride) {
            a0 += fabsf(ptr[i]);
            int j = i + 256;
            if (j < n) a1 += fabsf(ptr[j]);
        }
        sm[threadIdx.x] = (double)a0 + (double)a1;
        __syncthreads();
        for (int o = 128; o > 0; o >>= 1) {
            if (threadIdx.x < o) sm[threadIdx.x] += sm[threadIdx.x + o];
            __syncthreads();
        }
        if (threadIdx.x == 0) g_part[g][p] = sm[0];
    } else if (b < 3776) {               // ---- pack weights ----
        int wid = (b - 192)*8 + (threadIdx.x>>5);
        int lane = threadIdx.x & 31;
        if (wid < 9216) {
            int cw = wid & 3, kw = (wid>>2)%3, kh = (wid/12)%3, co = wid/36;
            float v = w1[(co*CI + cw*32 + lane)*9 + kh*3 + kw];
            uint bb = __ballot_sync(0xFFFFFFFFu, v >= 0.f);
            if (lane == 0) {
                g_w1bits[((kh*4 + cw)*CO + co)*4 + kw] = bb;
                if (kw == 0) g_w1bits[((kh*4 + cw)*CO + co)*4 + 3] = 0u;
            }
        } else if (wid < 9216 + 18432) {
            int id = wid - 9216;
            int cw = id & 7, kw = (id>>3)%3, kh = (id/24)%3, co = id/72;
            float v = w2[(co*CO + cw*32 + lane)*9 + kh*3 + kw];
            uint bb = __ballot_sync(0xFFFFFFFFu, v >= 0.f);
            if (lane == 0) {
                g_w2bits[((kh*8 + cw)*CO + co)*4 + kw] = bb;
                if (kw == 0) g_w2bits[((kh*8 + cw)*CO + co)*4 + 3] = 0u;
            }
        } else {
            int id = wid - 27648;
            int cw = id & 3, co = id >> 2;
            float v = ws[co*CI + cw*32 + lane];
            uint bb = __ballot_sync(0xFFFFFFFFu, v >= 0.f);
            if (lane == 0) g_wsbits[co*4 + cw] = bb;
        }
    } else {                             // ---- pack x signs ----
        const int t = b - 3776;
        const int n = t / Hh, h = t % Hh;
        const float* xp = x + ((size_t)n*CI*Hh + h)*Ww;
        for (int idx = threadIdx.x; idx < CI*(Ww/4); idx += 256) {
            int c = idx / (Ww/4), w4 = idx % (Ww/4);
            float4 v = *(const float4*)(xp + c*(Hh*Ww) + w4*4);
            uchar4 s;
            s.x = v.x >= 0.f; s.y = v.y >= 0.f; s.z = v.z >= 0.f; s.w = v.w >= 0.f;
            *(uchar4*)&sb[c][w4*4] = s;
        }
        __syncthreads();
        int warp = threadIdx.x >> 5, lane = threadIdx.x & 31;
        for (int tt = warp; tt < 4*Ww; tt += 8) {
            int cw = tt / Ww, w = tt % Ww;
            uint bb = __ballot_sync(0xFFFFFFFFu, sb[cw*32 + lane][w]);
            if (lane == 0) g_xbits[((n*4 + cw)*Hh + h)*Ww + w] = bb;
        }
    }
}

// conv1: half-row tiles (14 outputs), CSA quarters on phase-shifted copies.
__global__ void __launch_bounds__(256, 3) k_conv1() {
    __shared__ __align__(16) uint sP[3][4][32];   // P[j] = col 28h-1+j
    __shared__ __align__(16) uint sQ[3][4][32];   // Q[j] = col 28h+1+j
    __shared__ short st[CO*14];
    const int hb = blockIdx.x, oh = blockIdx.y, n = blockIdx.z, tid = threadIdx.x;
    const int c0 = 28*hb - 1;
    for (int idx = tid; idx < 3*4*32; idx += 256) {
        int kh = idx >> 7, cw = (idx >> 5) & 3, j = idx & 31;
        int r = 2*oh - 1 + kh;
        uint vP = 0, vQ = 0;
        if (r >= 0) {
            const uint* row = &g_xbits[((n*4 + cw)*Hh + r)*Ww];
            int cP = c0 + j, cQ = c0 + 2 + j;
            if (cP >= 0 && cP < Ww) vP = row[cP];
            if (cQ >= 0 && cQ < Ww) vQ = row[cQ];
        }
        sP[kh][cw][j] = vP;
        sQ[kh][cw][j] = vQ;
    }
    __syncthreads();

    int pwr[9];
#pragma unroll
    for (int i = 0; i < 9; i++) pwr[i] = 0;
    const int nrv = (oh == 0) ? 2 : 3;
    int psum = 0, psq = 0;

#pragma unroll 1
    for (int q = 0; q < 2; q++) {
        int acc[7];
        uint ones[7];
#pragma unroll
        for (int i = 0; i < 7; i++) { acc[i] = 0; ones[i] = 0u; }
#pragma unroll
        for (int kh = 0; kh < 3; kh++) {
#pragma unroll
            for (int cw = 0; cw < 4; cw++) {
                const uint* base = q ? &sQ[kh][cw][12] : &sP[kh][cw][0];
                uint X[16];
#pragma unroll
                for (int v = 0; v < 4; v++)
                    ((uint4*)X)[v] = *(const uint4*)(base + v*4);
                uint4 W = *(const uint4*)&g_w1bits[((kh*4 + cw)*CO + tid)*4];
                if (q == 0) {
                    pwr[kh*3 + 0] += __popc(W.x);
                    pwr[kh*3 + 1] += __popc(W.y);
                    pwr[kh*3 + 2] += __popc(W.z);
                }
#pragma unroll
                for (int i = 0; i < 7; i++) {
                    uint wa = X[2*i + 0] ^ W.x;
                    uint wb = X[2*i + 1] ^ W.y;
                    uint wc = X[2*i + 2] ^ W.z;
                    uint o  = ones[i];
                    uint cy = (o & wa) | (o & wb) | (wa & wb);
                    ones[i] = o ^ wa ^ wb;
                    acc[i] += 2*__popc(cy);
                    acc[i] += __popc(wc);
                }
            }
        }
        const int wc_row = (oh == 0) ? (pwr[0] + pwr[1] + pwr[2]) : 0;
#pragma unroll
        for (int i = 0; i < 7; i++) {
            int a = acc[i] + __popc(ones[i]);
            int owg = hb*14 + q*7 + i;
            int wc = wc_row, ncv = 3;
            if (owg == 0) {
                wc += pwr[3] + pwr[6] + ((oh == 0) ? 0 : pwr[0]);
                ncv = 2;
            }
            int S = 128*nrv*ncv - 2*(a - wc);
            st[tid*14 + q*7 + i] = (short)S;
            psum += S; psq += S*S;
        }
    }
    atomicAdd(&g_acc1[tid],      (ull)(ll)psum);
    atomicAdd(&g_acc1[CO + tid], (ull)(ll)psq);
    __syncthreads();
    for (int idx = tid; idx < CO*14; idx += 256) {
        int co = idx & (CO-1), owl = idx >> 8;
        g_S1t[((n*OH + oh)*OW + hb*14 + owl)*CO + co] = st[co*14 + owl];
    }
}

__global__ void k_bn1(const float* g1, const float* b1) {
    __shared__ float s_a1;
    if (threadIdx.x < 32) {
        double s = g_part[0][threadIdx.x] + g_part[0][threadIdx.x + 32];
        for (int o = 16; o > 0; o >>= 1) s += __shfl_down_sync(0xFFFFFFFFu, s, o);
        if (threadIdx.x == 0) s_a1 = (float)(s / (double)(CO*CI*9));
    }
    __syncthreads();
    int c = threadIdx.x;
    const double M = (double)M_EL;
    double a1 = (double)s_a1;
    double sum = (double)(ll)g_acc1[c];
    double ssq = (double)(ll)g_acc1[CO + c];
    double mS  = sum / M;
    double vS  = ssq / M - mS*mS;
    double inv = 1.0 / sqrt(a1*a1*vS + 1e-5);
    g_bn1a[c] = (float)((double)g1[c] * a1 * inv);
    g_bn1b[c] = (float)((double)b1[c] - (double)g1[c] * a1 * mS * inv);
}

__global__ void __launch_bounds__(256) k_packx2() {
    __shared__ unsigned char sb[OW][CO];
    __shared__ float sA[CO], sB[CO];
    const int n = blockIdx.x / OH, oh = blockIdx.x % OH;
    for (int i = threadIdx.x; i < CO; i += 256) { sA[i] = g_bn1a[i]; sB[i] = g_bn1b[i]; }
    __syncthreads();
    const short* sp = g_S1t + ((size_t)(n*OH + oh))*OW*CO;
    for (int idx = threadIdx.x; idx < OW*CO/4; idx += 256) {
        int e = idx*4, ow = e / CO, co = e % CO;
        int2 v = *(const int2*)(sp + e);
        uchar4 s;
        s.x = fmaf(sA[co],   (float)(short)(v.x),        sB[co])   >= 0.f;
        s.y = fmaf(sA[co+1], (float)(short)(v.x >> 16),  sB[co+1]) >= 0.f;
        s.z = fmaf(sA[co+2], (float)(short)(v.y),        sB[co+2]) >= 0.f;
        s.w = fmaf(sA[co+3], (float)(short)(v.y >> 16),  sB[co+3]) >= 0.f;
        *(uchar4*)&sb[ow][co] = s;
    }
    __syncthreads();
    int warp = threadIdx.x >> 5, lane = threadIdx.x & 31;
    for (int t = warp; t < 8*OW; t += 8) {
        int cw = t / OW, ow = t % OW;
        uint b = __ballot_sync(0xFFFFFFFFu, sb[ow][cw*32 + lane]);
        if (lane == 0) g_x2bits[((n*8 + cw)*OH + oh)*OW + ow] = b;
    }
}

// conv2 + shortcut: half-row tiles (14 outputs), single aligned 16-word window.
__global__ void __launch_bounds__(256, 3) k_conv2() {
    __shared__ __align__(16) uint sxw[3][8][16];  // sxw[j] = col 14h-1+j
    __shared__ uint ssc[4][14];
    __shared__ short st2[CO*14];
    __shared__ short sts[CO*14];
    const int hb = blockIdx.x, oh = blockIdx.y, n = blockIdx.z, tid = threadIdx.x;
    const int c0 = 14*hb - 1;
    for (int idx = tid; idx < 3*8*16; idx += 256) {
        int kh = idx >> 7, cw = (idx >> 4) & 7, j = idx & 15;
        int r = oh - 1 + kh, c = c0 + j;
        uint v = 0;
        if (r >= 0 && r < OH && c >= 0 && c < OW)
            v = g_x2bits[((n*8 + cw)*OH + r)*OW + c];
        sxw[kh][cw][j] = v;
    }
    for (int idx = tid; idx < 4*14; idx += 256) {
        int cw = idx / 14, owl = idx % 14;
        ssc[cw][owl] = g_xbits[((n*4 + cw)*Hh + 2*oh)*Ww + 2*(14*hb + owl)];
    }
    __syncthreads();

    uint4 wsv = *(const uint4*)&g_wsbits[tid*4];
    int pwr[9];
#pragma unroll
    for (int i = 0; i < 9; i++) pwr[i] = 0;
    int acc[14];
    uint ones[14];
#pragma unroll
    for (int i = 0; i < 14; i++) { acc[i] = 0; ones[i] = 0u; }

#pragma unroll
    for (int kh = 0; kh < 3; kh++) {
#pragma unroll
        for (int cw = 0; cw < 8; cw++) {
            uint X[16];
#pragma unroll
            for (int v = 0; v < 4; v++)
                ((uint4*)X)[v] = *(const uint4*)&sxw[kh][cw][v*4];
            uint4 W = *(const uint4*)&g_w2bits[((kh*8 + cw)*CO + tid)*4];
            pwr[kh*3 + 0] += __popc(W.x);
            pwr[kh*3 + 1] += __popc(W.y);
            pwr[kh*3 + 2] += __popc(W.z);
#pragma unroll
            for (int i = 0; i < 14; i++) {
                uint wa = X[i + 0] ^ W.x;
                uint wb = X[i + 1] ^ W.y;
                uint wc = X[i + 2] ^ W.z;
                uint o  = ones[i];
                uint cy = (o & wa) | (o & wb) | (wa & wb);
                ones[i] = o ^ wa ^ wb;
                acc[i] += 2*__popc(cy);
                acc[i] += __popc(wc);
            }
        }
    }

    const int nrv = 3 - (oh == 0) - (oh == OH-1);
    const int wc_row = ((oh == 0)    ? (pwr[0] + pwr[1] + pwr[2]) : 0)
                     + ((oh == OH-1) ? (pwr[6] + pwr[7] + pwr[8]) : 0);
    const int cl = pwr[3] + ((oh == 0) ? 0 : pwr[0]) + ((oh == OH-1) ? 0 : pwr[6]);
    const int cr = pwr[5] + ((oh == 0) ? 0 : pwr[2]) + ((oh == OH-1) ? 0 : pwr[8]);
    int p2 = 0, p22 = 0, ps = 0, pss = 0, p2s = 0;
#pragma unroll
    for (int owl = 0; owl < 14; owl++) {
        int ow = 14*hb + owl;
        int a = acc[owl] + __popc(ones[owl]);
        int wc = wc_row, ncv = 3;
        if (ow == 0)    { wc += cl; ncv = 2; }
        if (ow == OW-1) { wc += cr; ncv = 2; }
        int S2 = 256*nrv*ncv - 2*(a - wc);
        int accs = __popc(ssc[0][owl] ^ wsv.x) + __popc(ssc[1][owl] ^ wsv.y)
                 + __popc(ssc[2][owl] ^ wsv.z) + __popc(ssc[3][owl] ^ wsv.w);
        int Ss = 128 - 2*accs;
        st2[tid*14 + owl] = (short)S2;
        sts[tid*14 + owl] = (short)Ss;
        p2 += S2; p22 += S2*S2; ps += Ss; pss += Ss*Ss; p2s += S2*Ss;
    }
    atomicAdd(&g_acc2[tid],        (ull)(ll)p2);
    atomicAdd(&g_acc2[CO + tid],   (ull)(ll)p22);
    atomicAdd(&g_acc2[2*CO + tid], (ull)(ll)ps);
    atomicAdd(&g_acc2[3*CO + tid], (ull)(ll)pss);
    atomicAdd(&g_acc2[4*CO + tid], (ull)(ll)p2s);
    __syncthreads();
    for (int idx = tid; idx < CO*14; idx += 256) {
        int co = idx / 14, owl = idx % 14;
        int o = ((n*CO + co)*OH + oh)*OW + 14*hb + owl;
        g_S2[o] = st2[co*14 + owl];
        g_Ss[o] = sts[co*14 + owl];
    }
}

__global__ void k_bn2(const float* g2, const float* b2) {
    __shared__ float s_a2, s_as;
    if (threadIdx.x < 64) {
        int g = 1 + (threadIdx.x >> 5), lane = threadIdx.x & 31;
        double s = g_part[g][lane] + g_part[g][lane + 32];
        for (int o = 16; o > 0; o >>= 1) s += __shfl_down_sync(0xFFFFFFFFu, s, o);
        if (lane == 0) {
            if (g == 1) s_a2 = (float)(s / (double)(CO*CO*9));
            else        s_as = (float)(s / (double)(CO*CI));
        }
    }
    __syncthreads();
    int c = threadIdx.x;
    const double M = (double)M_EL;
    double a2 = (double)s_a2, as = (double)s_as;
    double s2  = (double)(ll)g_acc2[c];
    double s22 = (double)(ll)g_acc2[CO + c];
    double sS  = (double)(ll)g_acc2[2*CO + c];
    double sss = (double)(ll)g_acc2[3*CO + c];
    double s2s = (double)(ll)g_acc2[4*CO + c];
    double mu  = (a2*s2 + as*sS) / M;
    double E2  = (a2*a2*s22 + 2.0*a2*as*s2s + as*as*sss) / M;
    double var = E2 - mu*mu;
    double inv = 1.0 / sqrt(var + 1e-5);
    double sc  = (double)g2[c] * inv;
    g_A[c] = (float)(sc * a2);
    g_B[c] = (float)(sc * as);
    g_T[c] = (float)((double)b2[c] - sc * mu);
}

__global__ void k_final(float* out) {
    int i = (blockIdx.x*256 + threadIdx.x) * 8;
    int c = (i / (OH*OW)) & (CO-1);
    float A = g_A[c], B = g_B[c], T = g_T[c];
    const int4 a4 = *(const int4*)(g_S2 + i);
    const int4 s4 = *(const int4*)(g_Ss + i);
    float4 r0, r1;
    r0.x = fmaf(A, (float)(short)(a4.x),       fmaf(B, (float)(short)(s4.x),       T));
    r0.y = fmaf(A, (float)(short)(a4.x >> 16), fmaf(B, (float)(short)(s4.x >> 16), T));
    r0.z = fmaf(A, (float)(short)(a4.y),       fmaf(B, (float)(short)(s4.y),       T));
    r0.w = fmaf(A, (float)(short)(a4.y >> 16), fmaf(B, (float)(short)(s4.y >> 16), T));
    r1.x = fmaf(A, (float)(short)(a4.z),       fmaf(B, (float)(short)(s4.z),       T));
    r1.y = fmaf(A, (float)(short)(a4.z >> 16), fmaf(B, (float)(short)(s4.z >> 16), T));
    r1.z = fmaf(A, (float)(short)(a4.w),       fmaf(B, (float)(short)(s4.w),       T));
    r1.w = fmaf(A, (float)(short)(a4.w >> 16), fmaf(B, (float)(short)(s4.w >> 16), T));
    *(float4*)(out + i)     = r0;
    *(float4*)(out + i + 4) = r1;
}

// ---------------- launch ----------------
extern "C" void kernel_launch(void* const* d_in, const int* in_sizes, int n_in,
                              void* d_out, int out_size) {
    const float* x  = (const float*)d_in[0];
    const float* w1 = (const float*)d_in[1];
    const float* g1 = (const float*)d_in[2];
    const float* b1 = (const float*)d_in[3];
    const float* w2 = (const float*)d_in[4];
    const float* g2 = (const float*)d_in[5];
    const float* b2 = (const float*)d_in[6];
    const float* ws = (const float*)d_in[7];
    float* out = (float*)d_out;

    k_front<<<7360, 256>>>(x, w1, w2, ws);   // alpha + packw + packx + zero
    k_conv1<<<dim3(2, OH, Nn), 256>>>();     // 3584 half-row tiles (R13)
    k_bn1<<<1, 256>>>(g1, b1);
    k_packx2<<<Nn*OH, 256>>>();              // 4-wide (R14)
    k_conv2<<<dim3(2, OH, Nn), 256>>>();     // 3584 half-row tiles (R13)
    k_bn2<<<1, 256>>>(g2, b2);
    k_final<<<NOUT/8/256, 256>>>(out);       // 8 elems/thread (R14)
}

// round 17
// speedup vs baseline: 1.5761x; 1.5761x over previous
#include <cuda_runtime.h>
#include <cstdint>

typedef unsigned long long ull;
typedef long long ll;
typedef unsigned int uint;

// Problem dims
#define Nn   64
#define CI   128
#define Hh   56
#define Ww   56
#define CO   256
#define OH   28
#define OW   28
#define M_EL (Nn*OH*OW)
#define NOUT (Nn*CO*OH*OW)

// ---------------- device scratch ----------------
__device__ uint   g_xbits [Nn*4*Hh*Ww];     // [n][cw(4)][h][w]
__device__ uint   g_x2bits[Nn*8*OH*OW];     // [n][cw(8)][oh][ow]
__device__ uint   g_w1bits[3*4*CO*4];       // [kh][cw][co][kw(4, pad=0)]
__device__ uint   g_w2bits[3*8*CO*4];       // [kh][cw][co][kw(4, pad=0)]
__device__ uint   g_wsbits[CO*4];           // [co][cw(4)]
__device__ short  g_S1t[NOUT];              // [n][oh][ow][co]
__device__ short  g_S2[NOUT];               // NCHW
__device__ short  g_Ss[NOUT];               // NCHW
__device__ ull    g_acc1[2*CO];
__device__ ull    g_acc2[5*CO];
__device__ double g_part[3][64];
__device__ float  g_bn1a[CO], g_bn1b[CO];
__device__ float  g_A[CO], g_B[CO], g_T[CO];

// ---------------- fused front: alpha partials + weight pack + x pack ----------------
__global__ void __launch_bounds__(256) k_front(const float* x, const float* w1,
                                               const float* w2, const float* ws) {
    __shared__ double sm[256];
    __shared__ unsigned char sb[CI][Ww];
    const int b = blockIdx.x;

    if (b < 192) {                       // ---- alpha stage 1 ----
        if (b == 0) {
            for (int i = threadIdx.x; i < 2*CO; i += 256) g_acc1[i] = 0ull;
            for (int i = threadIdx.x; i < 5*CO; i += 256) g_acc2[i] = 0ull;
        }
        int g = b >> 6, p = b & 63;
        const float* ptr; int n;
        if (g == 0)      { ptr = w1; n = CO*CI*9; }
        else if (g == 1) { ptr = w2; n = CO*CO*9; }
        else             { ptr = ws; n = CO*CI;   }
        float a0 = 0.f, a1 = 0.f;
        int stride = 64*256*2;
        for (int i = p*512 + threadIdx.x; i < n; i += stride) {
            a0 += fabsf(ptr[i]);
            int j = i + 256;
            if (j < n) a1 += fabsf(ptr[j]);
        }
        sm[threadIdx.x] = (double)a0 + (double)a1;
        __syncthreads();
        for (int o = 128; o > 0; o >>= 1) {
            if (threadIdx.x < o) sm[threadIdx.x] += sm[threadIdx.x + o];
            __syncthreads();
        }
        if (threadIdx.x == 0) g_part[g][p] = sm[0];
    } else if (b < 3776) {               // ---- pack weights ----
        int wid = (b - 192)*8 + (threadIdx.x>>5);
        int lane = threadIdx.x & 31;
        if (wid < 9216) {
            int cw = wid & 3, kw = (wid>>2)%3, kh = (wid/12)%3, co = wid/36;
            float v = w1[(co*CI + cw*32 + lane)*9 + kh*3 + kw];
            uint bb = __ballot_sync(0xFFFFFFFFu, v >= 0.f);
            if (lane == 0) {
                g_w1bits[((kh*4 + cw)*CO + co)*4 + kw] = bb;
                if (kw == 0) g_w1bits[((kh*4 + cw)*CO + co)*4 + 3] = 0u;
            }
        } else if (wid < 9216 + 18432) {
            int id = wid - 9216;
            int cw = id & 7, kw = (id>>3)%3, kh = (id/24)%3, co = id/72;
            float v = w2[(co*CO + cw*32 + lane)*9 + kh*3 + kw];
            uint bb = __ballot_sync(0xFFFFFFFFu, v >= 0.f);
            if (lane == 0) {
                g_w2bits[((kh*8 + cw)*CO + co)*4 + kw] = bb;
                if (kw == 0) g_w2bits[((kh*8 + cw)*CO + co)*4 + 3] = 0u;
            }
        } else {
            int id = wid - 27648;
            int cw = id & 3, co = id >> 2;
            float v = ws[co*CI + cw*32 + lane];
            uint bb = __ballot_sync(0xFFFFFFFFu, v >= 0.f);
            if (lane == 0) g_wsbits[co*4 + cw] = bb;
        }
    } else {                             // ---- pack x signs ----
        const int t = b - 3776;
        const int n = t / Hh, h = t % Hh;
        const float* xp = x + ((size_t)n*CI*Hh + h)*Ww;
        for (int idx = threadIdx.x; idx < CI*(Ww/4); idx += 256) {
            int c = idx / (Ww/4), w4 = idx % (Ww/4);
            float4 v = *(const float4*)(xp + c*(Hh*Ww) + w4*4);
            uchar4 s;
            s.x = v.x >= 0.f; s.y = v.y >= 0.f; s.z = v.z >= 0.f; s.w = v.w >= 0.f;
            *(uchar4*)&sb[c][w4*4] = s;
        }
        __syncthreads();
        int warp = threadIdx.x >> 5, lane = threadIdx.x & 31;
        for (int tt = warp; tt < 4*Ww; tt += 8) {
            int cw = tt / Ww, w = tt % Ww;
            uint bb = __ballot_sync(0xFFFFFFFFu, sb[cw*32 + lane][w]);
            if (lane == 0) g_xbits[((n*4 + cw)*Hh + h)*Ww + w] = bb;
        }
    }
}

// conv1: half-row tiles (14 outputs), CSA quarters on phase-shifted copies.
__global__ void __launch_bounds__(256, 3) k_conv1() {
    __shared__ __align__(16) uint sP[3][4][32];   // P[j] = col 28h-1+j
    __shared__ __align__(16) uint sQ[3][4][32];   // Q[j] = col 28h+1+j
    __shared__ short st[CO*14];
    const int hb = blockIdx.x, oh = blockIdx.y, n = blockIdx.z, tid = threadIdx.x;
    const int c0 = 28*hb - 1;
    for (int idx = tid; idx < 3*4*32; idx += 256) {
        int kh = idx >> 7, cw = (idx >> 5) & 3, j = idx & 31;
        int r = 2*oh - 1 + kh;
        uint vP = 0, vQ = 0;
        if (r >= 0) {
            const uint* row = &g_xbits[((n*4 + cw)*Hh + r)*Ww];
            int cP = c0 + j, cQ = c0 + 2 + j;
            if (cP >= 0 && cP < Ww) vP = row[cP];
            if (cQ >= 0 && cQ < Ww) vQ = row[cQ];
        }
        sP[kh][cw][j] = vP;
        sQ[kh][cw][j] = vQ;
    }
    __syncthreads();

    int pwr[9];
#pragma unroll
    for (int i = 0; i < 9; i++) pwr[i] = 0;
    const int nrv = (oh == 0) ? 2 : 3;
    int psum = 0, psq = 0;

#pragma unroll 1
    for (int q = 0; q < 2; q++) {
        int acc[7];
        uint ones[7];
#pragma unroll
        for (int i = 0; i < 7; i++) { acc[i] = 0; ones[i] = 0u; }
#pragma unroll
        for (int kh = 0; kh < 3; kh++) {
#pragma unroll
            for (int cw = 0; cw < 4; cw++) {
                const uint* base = q ? &sQ[kh][cw][12] : &sP[kh][cw][0];
                uint X[16];
#pragma unroll
                for (int v = 0; v < 4; v++)
                    ((uint4*)X)[v] = *(const uint4*)(base + v*4);
                uint4 W = *(const uint4*)&g_w1bits[((kh*4 + cw)*CO + tid)*4];
                if (q == 0) {
                    pwr[kh*3 + 0] += __popc(W.x);
                    pwr[kh*3 + 1] += __popc(W.y);
                    pwr[kh*3 + 2] += __popc(W.z);
                }
#pragma unroll
                for (int i = 0; i < 7; i++) {
                    uint wa = X[2*i + 0] ^ W.x;
                    uint wb = X[2*i + 1] ^ W.y;
                    uint wc = X[2*i + 2] ^ W.z;
                    uint o  = ones[i];
                    uint cy = (o & wa) | (o & wb) | (wa & wb);
                    ones[i] = o ^ wa ^ wb;
                    acc[i] += 2*__popc(cy);
                    acc[i] += __popc(wc);
                }
            }
        }
        const int wc_row = (oh == 0) ? (pwr[0] + pwr[1] + pwr[2]) : 0;
#pragma unroll
        for (int i = 0; i < 7; i++) {
            int a = acc[i] + __popc(ones[i]);
            int owg = hb*14 + q*7 + i;
            int wc = wc_row, ncv = 3;
            if (owg == 0) {
                wc += pwr[3] + pwr[6] + ((oh == 0) ? 0 : pwr[0]);
                ncv = 2;
            }
            int S = 128*nrv*ncv - 2*(a - wc);
            st[tid*14 + q*7 + i] = (short)S;
            psum += S; psq += S*S;
        }
    }
    atomicAdd(&g_acc1[tid],      (ull)(ll)psum);
    atomicAdd(&g_acc1[CO + tid], (ull)(ll)psq);
    __syncthreads();
    for (int idx = tid; idx < CO*14; idx += 256) {
        int co = idx & (CO-1), owl = idx >> 8;
        g_S1t[((n*OH + oh)*OW + hb*14 + owl)*CO + co] = st[co*14 + owl];
    }
}

__global__ void k_bn1(const float* g1, const float* b1) {
    __shared__ float s_a1;
    if (threadIdx.x < 32) {
        double s = g_part[0][threadIdx.x] + g_part[0][threadIdx.x + 32];
        for (int o = 16; o > 0; o >>= 1) s += __shfl_down_sync(0xFFFFFFFFu, s, o);
        if (threadIdx.x == 0) s_a1 = (float)(s / (double)(CO*CI*9));
    }
    __syncthreads();
    int c = threadIdx.x;
    const double M = (double)M_EL;
    double a1 = (double)s_a1;
    double sum = (double)(ll)g_acc1[c];
    double ssq = (double)(ll)g_acc1[CO + c];
    double mS  = sum / M;
    double vS  = ssq / M - mS*mS;
    double inv = 1.0 / sqrt(a1*a1*vS + 1e-5);
    g_bn1a[c] = (float)((double)g1[c] * a1 * inv);
    g_bn1b[c] = (float)((double)b1[c] - (double)g1[c] * a1 * mS * inv);
}

__global__ void __launch_bounds__(256) k_packx2() {
    __shared__ unsigned char sb[OW][CO];
    __shared__ float sA[CO], sB[CO];
    const int n = blockIdx.x / OH, oh = blockIdx.x % OH;
    for (int i = threadIdx.x; i < CO; i += 256) { sA[i] = g_bn1a[i]; sB[i] = g_bn1b[i]; }
    __syncthreads();
    const short* sp = g_S1t + ((size_t)(n*OH + oh))*OW*CO;
    for (int idx = threadIdx.x; idx < OW*CO/4; idx += 256) {
        int e = idx*4, ow = e / CO, co = e % CO;
        int2 v = *(const int2*)(sp + e);
        uchar4 s;
        s.x = fmaf(sA[co],   (float)(short)(v.x),        sB[co])   >= 0.f;
        s.y = fmaf(sA[co+1], (float)(short)(v.x >> 16),  sB[co+1]) >= 0.f;
        s.z = fmaf(sA[co+2], (float)(short)(v.y),        sB[co+2]) >= 0.f;
        s.w = fmaf(sA[co+3], (float)(short)(v.y >> 16),  sB[co+3]) >= 0.f;
        *(uchar4*)&sb[ow][co] = s;
    }
    __syncthreads();
    int warp = threadIdx.x >> 5, lane = threadIdx.x & 31;
    for (int t = warp; t < 8*OW; t += 8) {
        int cw = t / OW, ow = t % OW;
        uint b = __ballot_sync(0xFFFFFFFFu, sb[ow][cw*32 + lane]);
        if (lane == 0) g_x2bits[((n*8 + cw)*OH + oh)*OW + ow] = b;
    }
}

// conv2 + shortcut: half-row tiles (14 outputs), single aligned 16-word window.
__global__ void __launch_bounds__(256, 3) k_conv2() {
    __shared__ __align__(16) uint sxw[3][8][16];  // sxw[j] = col 14h-1+j
    __shared__ uint ssc[4][14];
    __shared__ short st2[CO*14];
    __shared__ short sts[CO*14];
    const int hb = blockIdx.x, oh = blockIdx.y, n = blockIdx.z, tid = threadIdx.x;
    const int c0 = 14*hb - 1;
    for (int idx = tid; idx < 3*8*16; idx += 256) {
        int kh = idx >> 7, cw = (idx >> 4) & 7, j = idx & 15;
        int r = oh - 1 + kh, c = c0 + j;
        uint v = 0;
        if (r >= 0 && r < OH && c >= 0 && c < OW)
            v = g_x2bits[((n*8 + cw)*OH + r)*OW + c];
        sxw[kh][cw][j] = v;
    }
    for (int idx = tid; idx < 4*14; idx += 256) {
        int cw = idx / 14, owl = idx % 14;
        ssc[cw][owl] = g_xbits[((n*4 + cw)*Hh + 2*oh)*Ww + 2*(14*hb + owl)];
    }
    __syncthreads();

    uint4 wsv = *(const uint4*)&g_wsbits[tid*4];
    int pwr[9];
#pragma unroll
    for (int i = 0; i < 9; i++) pwr[i] = 0;
    int acc[14];
    uint ones[14];
#pragma unroll
    for (int i = 0; i < 14; i++) { acc[i] = 0; ones[i] = 0u; }

#pragma unroll
    for (int kh = 0; kh < 3; kh++) {
#pragma unroll
        for (int cw = 0; cw < 8; cw++) {
            uint X[16];
#pragma unroll
            for (int v = 0; v < 4; v++)
                ((uint4*)X)[v] = *(const uint4*)&sxw[kh][cw][v*4];
            uint4 W = *(const uint4*)&g_w2bits[((kh*8 + cw)*CO + tid)*4];
            pwr[kh*3 + 0] += __popc(W.x);
            pwr[kh*3 + 1] += __popc(W.y);
            pwr[kh*3 + 2] += __popc(W.z);
#pragma unroll
            for (int i = 0; i < 14; i++) {
                uint wa = X[i + 0] ^ W.x;
                uint wb = X[i + 1] ^ W.y;
                uint wc = X[i + 2] ^ W.z;
                uint o  = ones[i];
                uint cy = (o & wa) | (o & wb) | (wa & wb);
                ones[i] = o ^ wa ^ wb;
                acc[i] += 2*__popc(cy);
                acc[i] += __popc(wc);
            }
        }
    }

    const int nrv = 3 - (oh == 0) - (oh == OH-1);
    const int wc_row = ((oh == 0)    ? (pwr[0] + pwr[1] + pwr[2]) : 0)
                     + ((oh == OH-1) ? (pwr[6] + pwr[7] + pwr[8]) : 0);
    const int cl = pwr[3] + ((oh == 0) ? 0 : pwr[0]) + ((oh == OH-1) ? 0 : pwr[6]);
    const int cr = pwr[5] + ((oh == 0) ? 0 : pwr[2]) + ((oh == OH-1) ? 0 : pwr[8]);
    int p2 = 0, p22 = 0, ps = 0, pss = 0, p2s = 0;
#pragma unroll
    for (int owl = 0; owl < 14; owl++) {
        int ow = 14*hb + owl;
        int a = acc[owl] + __popc(ones[owl]);
        int wc = wc_row, ncv = 3;
        if (ow == 0)    { wc += cl; ncv = 2; }
        if (ow == OW-1) { wc += cr; ncv = 2; }
        int S2 = 256*nrv*ncv - 2*(a - wc);
        int accs = __popc(ssc[0][owl] ^ wsv.x) + __popc(ssc[1][owl] ^ wsv.y)
                 + __popc(ssc[2][owl] ^ wsv.z) + __popc(ssc[3][owl] ^ wsv.w);
        int Ss = 128 - 2*accs;
        st2[tid*14 + owl] = (short)S2;
        sts[tid*14 + owl] = (short)Ss;
        p2 += S2; p22 += S2*S2; ps += Ss; pss += Ss*Ss; p2s += S2*Ss;
    }
    atomicAdd(&g_acc2[tid],        (ull)(ll)p2);
    atomicAdd(&g_acc2[CO + tid],   (ull)(ll)p22);
    atomicAdd(&g_acc2[2*CO + tid], (ull)(ll)ps);
    atomicAdd(&g_acc2[3*CO + tid], (ull)(ll)pss);
    atomicAdd(&g_acc2[4*CO + tid], (ull)(ll)p2s);
    __syncthreads();
    for (int idx = tid; idx < CO*14; idx += 256) {
        int co = idx / 14, owl = idx % 14;
        int o = ((n*CO + co)*OH + oh)*OW + 14*hb + owl;
        g_S2[o] = st2[co*14 + owl];
        g_Ss[o] = sts[co*14 + owl];
    }
}

__global__ void k_bn2(const float* g2, const float* b2) {
    __shared__ float s_a2, s_as;
    if (threadIdx.x < 64) {
        int g = 1 + (threadIdx.x >> 5), lane = threadIdx.x & 31;
        double s = g_part[g][lane] + g_part[g][lane + 32];
        for (int o = 16; o > 0; o >>= 1) s += __shfl_down_sync(0xFFFFFFFFu, s, o);
        if (lane == 0) {
            if (g == 1) s_a2 = (float)(s / (double)(CO*CO*9));
            else        s_as = (float)(s / (double)(CO*CI));
        }
    }
    __syncthreads();
    int c = threadIdx.x;
    const double M = (double)M_EL;
    double a2 = (double)s_a2, as = (double)s_as;
    double s2  = (double)(ll)g_acc2[c];
    double s22 = (double)(ll)g_acc2[CO + c];
    double sS  = (double)(ll)g_acc2[2*CO + c];
    double sss = (double)(ll)g_acc2[3*CO + c];
    double s2s = (double)(ll)g_acc2[4*CO + c];
    double mu  = (a2*s2 + as*sS) / M;
    double E2  = (a2*a2*s22 + 2.0*a2*as*s2s + as*as*sss) / M;
    double var = E2 - mu*mu;
    double inv = 1.0 / sqrt(var + 1e-5);
    double sc  = (double)g2[c] * inv;
    g_A[c] = (float)(sc * a2);
    g_B[c] = (float)(sc * as);
    g_T[c] = (float)((double)b2[c] - sc * mu);
}

__global__ void k_final(float* out) {
    int i = (blockIdx.x*256 + threadIdx.x) * 8;
    int c = (i / (OH*OW)) & (CO-1);
    float A = g_A[c], B = g_B[c], T = g_T[c];
    const int4 a4 = *(const int4*)(g_S2 + i);
    const int4 s4 = *(const int4*)(g_Ss + i);
    float4 r0, r1;
    r0.x = fmaf(A, (float)(short)(a4.x),       fmaf(B, (float)(short)(s4.x),       T));
    r0.y = fmaf(A, (float)(short)(a4.x >> 16), fmaf(B, (float)(short)(s4.x >> 16), T));
    r0.z = fmaf(A, (float)(short)(a4.y),       fmaf(B, (float)(short)(s4.y),       T));
    r0.w = fmaf(A, (float)(short)(a4.y >> 16), fmaf(B, (float)(short)(s4.y >> 16), T));
    r1.x = fmaf(A, (float)(short)(a4.z),       fmaf(B, (float)(short)(s4.z),       T));
    r1.y = fmaf(A, (float)(short)(a4.z >> 16), fmaf(B, (float)(short)(s4.z >> 16), T));
    r1.z = fmaf(A, (float)(short)(a4.w),       fmaf(B, (float)(short)(s4.w),       T));
    r1.w = fmaf(A, (float)(short)(a4.w >> 16), fmaf(B, (float)(short)(s4.w >> 16), T));
    *(float4*)(out + i)     = r0;
    *(float4*)(out + i + 4) = r1;
}

// ---------------- launch ----------------
extern "C" void kernel_launch(void* const* d_in, const int* in_sizes, int n_in,
                              void* d_out, int out_size) {
    const float* x  = (const float*)d_in[0];
    const float* w1 = (const float*)d_in[1];
    const float* g1 = (const float*)d_in[2];
    const float* b1 = (const float*)d_in[3];
    const float* w2 = (const float*)d_in[4];
    const float* g2 = (const float*)d_in[5];
    const float* b2 = (const float*)d_in[6];
    const float* ws = (const float*)d_in[7];
    float* out = (float*)d_out;

    k_front<<<7360, 256>>>(x, w1, w2, ws);   // alpha + packw + packx + zero
    k_conv1<<<dim3(2, OH, Nn), 256>>>();     // 3584 half-row tiles (R13)
    k_bn1<<<1, 256>>>(g1, b1);
    k_packx2<<<Nn*OH, 256>>>();              // 4-wide (R14)
    k_conv2<<<dim3(2, OH, Nn), 256>>>();     // 3584 half-row tiles (R13)
    k_bn2<<<1, 256>>>(g2, b2);
    k_final<<<NOUT/8/256, 256>>>(out);       // 8 elems/thread (R14)
}